// round 6
// baseline (speedup 1.0000x reference)
#include <cuda_runtime.h>
#include <stdint.h>

// Problem constants
#define BB 4
#define XX 32
#define HH 8
#define WW 128
#define CC 32
#define NQ 128          // distinct query rows per batch
#define MM 4096         // key rows per batch
#define DD 256          // reduction dim

// Scratch (plain fp32 row-major everywhere)
__device__ __align__(16) float g_Q [BB*NQ*DD];    // [b][n][cc]
__device__ __align__(16) float g_K [BB*MM*DD];    // [b][m][cc]
__device__ __align__(16) float g_V [BB*MM*DD];    // [b][m][cc]
__device__ __align__(16) float g_Vt[BB*DD*MM];    // [b][cc][m]
__device__ __align__(16) float g_E [BB*NQ*MM];    // [b][n][m] = exp(S)
__device__ __align__(16) float g_O [BB*NQ*DD];
__device__ __align__(16) float g_rowsum[BB*NQ];
__device__ __align__(16) float g_Wh[96*72];       // presplit conv weights [k][o]
__device__ __align__(16) float g_Wl[96*72];

// ---------------------------------------------------------------------------
// helpers
// ---------------------------------------------------------------------------
__device__ __forceinline__ uint32_t f2tf(float x) {
    uint32_t h; asm("cvt.rna.tf32.f32 %0, %1;" : "=r"(h) : "f"(x)); return h;
}
__device__ __forceinline__ void sts_split(float v, float* ph, float* pl) {
    float hf = __uint_as_float(f2tf(v));
    *ph = hf;
    *pl = __uint_as_float(f2tf(v - hf));
}
// cheap register split: hi = mask13(f) (bits HMMA reads), lo = f - hi (exact)
__device__ __forceinline__ void split2(float f, uint32_t& hi, uint32_t& lo) {
    uint32_t h = __float_as_uint(f) & 0xFFFFE000u;
    hi = h;
    lo = __float_as_uint(f - __uint_as_float(h));
}
__device__ __forceinline__ void mma8(float4& d, const uint32_t* a,
                                     uint32_t b0, uint32_t b1) {
    asm volatile(
        "mma.sync.aligned.m16n8k8.row.col.f32.tf32.tf32.f32 "
        "{%0,%1,%2,%3},{%4,%5,%6,%7},{%8,%9},{%0,%1,%2,%3};"
        : "+f"(d.x), "+f"(d.y), "+f"(d.z), "+f"(d.w)
        : "r"(a[0]), "r"(a[1]), "r"(a[2]), "r"(a[3]), "r"(b0), "r"(b1));
}
__device__ __forceinline__ uint32_t smaddr(const void* p) {
    return (uint32_t)__cvta_generic_to_shared(p);
}
__device__ __forceinline__ void ldsm4(uint32_t r[4], const float* p) {
    uint32_t a = smaddr(p);
    asm volatile("ldmatrix.sync.aligned.m8n8.x4.shared.b16 {%0,%1,%2,%3}, [%4];"
                 : "=r"(r[0]), "=r"(r[1]), "=r"(r[2]), "=r"(r[3]) : "r"(a));
}
__device__ __forceinline__ void ldsm2(uint32_t r[2], const float* p) {
    uint32_t a = smaddr(p);
    asm volatile("ldmatrix.sync.aligned.m8n8.x2.shared.b16 {%0,%1}, [%2];"
                 : "=r"(r[0]), "=r"(r[1]) : "r"(a));
}
#define CPA(dst, src) asm volatile("cp.async.cg.shared.global [%0], [%1], 16;" \
                                   :: "r"(dst), "l"(src))
#define CP_COMMIT() asm volatile("cp.async.commit_group;")

// ---------------------------------------------------------------------------
// Kernel 1: Q projection (plain fp32) + zero g_O/g_rowsum + presplit conv wts
// ---------------------------------------------------------------------------
__global__ __launch_bounds__(256) void k_q(const float* __restrict__ target,
                                           const float* __restrict__ w_q,
                                           const float* __restrict__ b_q,
                                           const float* __restrict__ w_cross) {
    int t = blockIdx.x * 256 + threadIdx.x;       // [0, 131072)
    g_O[t] = 0.f;
    if (t < BB*NQ) g_rowsum[t] = 0.f;
    if (t < 96*72) {
        int k = t / 72, o = t - k*72;
        float v = (o < 64) ? w_cross[(o*32 + (k & 31))*3 + (k >> 5)] : 0.f;
        sts_split(v, &g_Wh[t], &g_Wl[t]);
    }

    int b   = t >> 15;
    int n   = (t >> 8) & 127;
    int cc  = t & 255;
    int o   = n >> 2, whi = n & 3;
    int wlo = cc >> 3, h = cc & 7;
    int w   = whi * 32 + wlo;
    const float4* trow = (const float4*)(target + ((b*HH + h)*WW + w)*CC);
    const float4* wrow = (const float4*)(w_q + o*CC);
    float acc = b_q[o];
#pragma unroll
    for (int i = 0; i < 8; i++) {
        float4 a = trow[i], ww = wrow[i];
        acc += a.x*ww.x + a.y*ww.y + a.z*ww.z + a.w*ww.w;
    }
    g_Q[t] = acc;
}

// ---------------------------------------------------------------------------
// Kernel 2: conv3d (3,1,1) im2col GEMM (3xTF32). Plain row-major K/V stores.
// ---------------------------------------------------------------------------
#define CONV_SMEM_FLOATS (2*18*264 + 2*96*72 + 64)
__global__ __launch_bounds__(256) void k_conv(const float* __restrict__ storage,
                                              const float* __restrict__ b_cross) {
    extern __shared__ float sm[];
    float* Sh  = sm;                    // 18*264
    float* Sl  = Sh + 18*264;
    float* Wh  = Sl + 18*264;           // 96*72
    float* Wl  = Wh + 96*72;
    float* bsh = Wl + 96*72;            // 64

    int tid  = threadIdx.x;
    int bidx = blockIdx.x;              // b*256 + w*2 + xh
    int b  = bidx >> 8;
    int w  = (bidx >> 1) & 127;
    int xh = bidx & 1;
    int x0 = xh * 16;

    {
        const float4* sh4 = (const float4*)g_Wh;
        const float4* sl4 = (const float4*)g_Wl;
        float4* dh4 = (float4*)Wh;
        float4* dl4 = (float4*)Wl;
        for (int i = tid; i < 1728; i += 256) { dh4[i] = sh4[i]; dl4[i] = sl4[i]; }
    }
    if (tid < 64) bsh[tid] = b_cross[tid];

    for (int i = tid; i < 18*64; i += 256) {
        int si = i >> 6, r = i & 63;
        int c4 = (r & 7)*4, h = r >> 3;
        int xx = x0 - 1 + si;
        float4 v = make_float4(0.f, 0.f, 0.f, 0.f);
        if (xx >= 0 && xx < XX)
            v = *(const float4*)(storage + (((b*XX + xx)*HH + h)*WW + w)*CC + c4);
        float* ph = Sh + si*264 + c4*8 + h;
        float* pl = Sl + si*264 + c4*8 + h;
        sts_split(v.x, ph +  0, pl +  0);
        sts_split(v.y, ph +  8, pl +  8);
        sts_split(v.z, ph + 16, pl + 16);
        sts_split(v.w, ph + 24, pl + 24);
    }
    __syncthreads();

    int lane = tid & 31, ww = tid >> 5;
    int lr = lane >> 2, lc = lane & 3;
    int wm = ww & 3, wn = ww >> 2;      // 4m x 2n warps; warp tile 32x32
    float4 acc[2][4];
#pragma unroll
    for (int i = 0; i < 2; i++)
#pragma unroll
        for (int j = 0; j < 4; j++) acc[i][j] = make_float4(0.f,0.f,0.f,0.f);

#pragma unroll
    for (int ksl = 0; ksl < 12; ksl++) {
        int k0 = ksl*8;
        int dx = k0 >> 5, cib = k0 & 31;
        uint32_t ah[2][4], al[2][4];
#pragma unroll
        for (int mt = 0; mt < 2; mt++) {
            int rowb = wm*32 + mt*16;
            int xl = rowb >> 3;
            const float* p = Sh + (xl + dx)*264 + (cib + lc)*8 + lr;
            ah[mt][0] = __float_as_uint(p[0]);
            ah[mt][1] = __float_as_uint(p[264]);
            ah[mt][2] = __float_as_uint(p[32]);
            ah[mt][3] = __float_as_uint(p[264+32]);
            const float* q = Sl + (xl + dx)*264 + (cib + lc)*8 + lr;
            al[mt][0] = __float_as_uint(q[0]);
            al[mt][1] = __float_as_uint(q[264]);
            al[mt][2] = __float_as_uint(q[32]);
            al[mt][3] = __float_as_uint(q[264+32]);
        }
#pragma unroll
        for (int nt = 0; nt < 4; nt++) {
            int nb = wn*32 + nt*8;
            const float* p = Wh + (k0 + lc)*72 + nb + lr;
            uint32_t bh0 = __float_as_uint(p[0]);
            uint32_t bh1 = __float_as_uint(p[4*72]);
            const float* q = Wl + (k0 + lc)*72 + nb + lr;
            uint32_t bl0 = __float_as_uint(q[0]);
            uint32_t bl1 = __float_as_uint(q[4*72]);
#pragma unroll
            for (int mt = 0; mt < 2; mt++) {
                mma8(acc[mt][nt], ah[mt], bh0, bh1);
                mma8(acc[mt][nt], ah[mt], bl0, bl1);
                mma8(acc[mt][nt], al[mt], bh0, bh1);
            }
        }
    }

    int wb = w >> 5, ccb = (w & 31)*8;
#pragma unroll
    for (int mt = 0; mt < 2; mt++) {
        int rowb = wm*32 + mt*16;
        int x = x0 + (rowb >> 3);
        int h = lr;
#pragma unroll
        for (int nt = 0; nt < 4; nt++) {
            int o0 = wn*32 + nt*8 + lc*2;
            float4 d = acc[mt][nt];
            {
                float v0 = d.x + bsh[o0], v1 = d.y + bsh[o0+1];
                float* d0 = (o0     < 32) ? g_V : g_K;
                float* d1 = (o0 + 1 < 32) ? g_V : g_K;
                d0[(b*MM + (o0&31)*128     + x*4 + wb)*DD + ccb + h] = v0;
                d1[(b*MM + ((o0+1)&31)*128 + x*4 + wb)*DD + ccb + h] = v1;
            }
            {
                float v0 = d.z + bsh[o0], v1 = d.w + bsh[o0+1];
                float* d0 = (o0     < 32) ? g_V : g_K;
                float* d1 = (o0 + 1 < 32) ? g_V : g_K;
                d0[(b*MM + (o0&31)*128     + (x+1)*4 + wb)*DD + ccb + h] = v0;
                d1[(b*MM + ((o0+1)&31)*128 + (x+1)*4 + wb)*DD + ccb + h] = v1;
            }
        }
    }
}

// ---------------------------------------------------------------------------
// Kernel 3: V transpose  [b][m][cc] -> [b][cc][m], 64x64 tiles, coalesced.
// ---------------------------------------------------------------------------
__global__ __launch_bounds__(256) void k_vt() {
    __shared__ float ts[64*65];
    int tid = threadIdx.x;
    int b  = blockIdx.x >> 8;
    int mt = (blockIdx.x >> 2) & 63;
    int ct = blockIdx.x & 3;
#pragma unroll
    for (int it = 0; it < 4; it++) {
        int i = tid + it*256;               // 0..1023
        int r = i >> 4, c4 = (i & 15)*4;
        float4 v = *(const float4*)(g_V + (b*MM + mt*64 + r)*DD + ct*64 + c4);
        ts[r*65 + c4 + 0] = v.x; ts[r*65 + c4 + 1] = v.y;
        ts[r*65 + c4 + 2] = v.z; ts[r*65 + c4 + 3] = v.w;
    }
    __syncthreads();
#pragma unroll
    for (int it = 0; it < 4; it++) {
        int i = tid + it*256;
        int c = i >> 4, r4 = (i & 15)*4;
        float4 o = make_float4(ts[(r4+0)*65 + c], ts[(r4+1)*65 + c],
                               ts[(r4+2)*65 + c], ts[(r4+3)*65 + c]);
        *(float4*)(g_Vt + (b*DD + ct*64 + c)*MM + mt*64 + r4) = o;
    }
}

// ---------------------------------------------------------------------------
// GEMM machinery: fp32 smem tiles [128][32] stride 36, cp.async staging,
// ldmatrix frags, mask-based in-register 3xTF32 split. 512 threads/CTA.
// ---------------------------------------------------------------------------
#define ASTR 36
#define STAGE_FLOATS (2*128*ASTR)           // A + B tile = 9216
#define GEMM_SMEM_BYTES (2*STAGE_FLOATS*4)  // double buffered = 73728 B

__device__ __forceinline__ void copy_stage(float* buf, const float* Ag, int lda,
                                           const float* Bg, int ldb, int tid) {
#pragma unroll
    for (int ch = 0; ch < 4; ch++) {
        int c = tid + ch*512;               // 0..2047
        int row = c >> 3, k4 = (c & 7)*4;
        if (row < 128)
            CPA(smaddr(buf + row*ASTR + k4), Ag + row*lda + k4);
        else
            CPA(smaddr(buf + 128*ASTR + (row-128)*ASTR + k4),
                Bg + (row-128)*ldb + k4);
    }
    CP_COMMIT();
}

// one 32-k stage; warp tile 32m x 32n (wm 0..3, wn 0..3)
__device__ __forceinline__ void stage_mma(const float* buf, float4 acc[2][4],
                                          int lane, int wm, int wn) {
    const float* As = buf;
    const float* Bs = buf + 128*ASTR;
    int arow = (lane & 7) + ((lane >> 3) & 1)*8;
    int acol = (lane >> 4)*4;
    int bl   = lane & 15;
    int brow = bl & 7;
    int bcol = (bl >> 3)*4;
#pragma unroll
    for (int kt = 0; kt < 4; kt++) {
        int kk = kt*8;
        uint32_t ahH[2][4], ahL[2][4];
#pragma unroll
        for (int mt = 0; mt < 2; mt++) {
            int rb = wm*32 + mt*16;
            uint32_t ar[4];
            ldsm4(ar, As + (rb + arow)*ASTR + kk + acol);
#pragma unroll
            for (int i = 0; i < 4; i++)
                split2(__uint_as_float(ar[i]), ahH[mt][i], ahL[mt][i]);
        }
#pragma unroll
        for (int nt = 0; nt < 4; nt++) {
            int nrb = wn*32 + nt*8;
            uint32_t br[2];
            ldsm2(br, Bs + (nrb + brow)*ASTR + kk + bcol);
            uint32_t bh0, bL0, bh1, bL1;
            split2(__uint_as_float(br[0]), bh0, bL0);
            split2(__uint_as_float(br[1]), bh1, bL1);
#pragma unroll
            for (int mt = 0; mt < 2; mt++) {
                mma8(acc[mt][nt], ahH[mt], bh0, bh1);
                mma8(acc[mt][nt], ahH[mt], bL0, bL1);
                mma8(acc[mt][nt], ahL[mt], bh0, bh1);
            }
        }
    }
}

// ---------------------------------------------------------------------------
// Kernel 4: S = Q @ K^T (3xTF32), fused exp + rowsum, E fp32 out. 512 thr.
// grid = b(4) x nb(32); CTA tile 128q x 128k; K = 256 (8 stages of 32).
// ---------------------------------------------------------------------------
__global__ __launch_bounds__(512, 1) void k_gemm1() {
    extern __shared__ float sm[];
    __shared__ float srow[128];
    int tid = threadIdx.x;
    int b  = blockIdx.x >> 5;
    int nb = blockIdx.x & 31;
    const float* Ag = g_Q + b*NQ*DD;
    const float* Bg = g_K + (b*MM + nb*128)*DD;

    int lane = tid & 31, ww = tid >> 5;
    int lr = lane >> 2, lc = lane & 3;
    int wm = ww & 3, wn = ww >> 2;
    float4 acc[2][4];
#pragma unroll
    for (int i = 0; i < 2; i++)
#pragma unroll
        for (int j = 0; j < 4; j++) acc[i][j] = make_float4(0.f,0.f,0.f,0.f);

    copy_stage(sm, Ag, DD, Bg, DD, tid);
    for (int s = 0; s < 8; s++) {
        if (s < 7)
            copy_stage(sm + ((s+1)&1)*STAGE_FLOATS,
                       Ag + (s+1)*32, DD, Bg + (s+1)*32, DD, tid);
        if (s < 7) asm volatile("cp.async.wait_group 1;");
        else       asm volatile("cp.async.wait_group 0;");
        __syncthreads();
        stage_mma(sm + (s&1)*STAGE_FLOATS, acc, lane, wm, wn);
        __syncthreads();
    }

    if (tid < 128) srow[tid] = 0.f;
    __syncthreads();
    float* Eg = g_E + b*NQ*MM + nb*128;
    float rs[4] = {0.f,0.f,0.f,0.f};
#pragma unroll
    for (int mt = 0; mt < 2; mt++) {
#pragma unroll
        for (int nt = 0; nt < 4; nt++) {
            int row = wm*32 + mt*16 + lr;
            int col = wn*32 + nt*8 + lc*2;
            float4 d = acc[mt][nt];
            float e0 = __expf(d.x), e1 = __expf(d.y);
            float e2 = __expf(d.z), e3 = __expf(d.w);
            rs[mt*2+0] += e0 + e1;
            rs[mt*2+1] += e2 + e3;
            *(float2*)(Eg + row*MM + col)     = make_float2(e0, e1);
            *(float2*)(Eg + (row+8)*MM + col) = make_float2(e2, e3);
        }
    }
#pragma unroll
    for (int i = 0; i < 4; i++) {
        rs[i] += __shfl_xor_sync(~0u, rs[i], 1);
        rs[i] += __shfl_xor_sync(~0u, rs[i], 2);
    }
    if (lc == 0) {
#pragma unroll
        for (int i = 0; i < 4; i++)
            atomicAdd(&srow[wm*32 + (i >> 1)*16 + (i & 1)*8 + lr], rs[i]);
    }
    __syncthreads();
    if (tid < 128) atomicAdd(&g_rowsum[b*128 + tid], srow[tid]);
}

// ---------------------------------------------------------------------------
// Kernel 5: O += E @ V (3xTF32), split-K(m) atomics. 512 thr.
// grid = b(4) x nb(2) x ks(16). A = E [n][m]; B = Vt [cc][m].
// ---------------------------------------------------------------------------
__global__ __launch_bounds__(512, 1) void k_gemm2() {
    extern __shared__ float sm[];
    int tid = threadIdx.x;
    int b  = blockIdx.x >> 5;
    int nb = (blockIdx.x >> 4) & 1;
    int ks = blockIdx.x & 15;
    const float* Ag = g_E  + b*NQ*MM + ks*256;
    const float* Bg = g_Vt + (b*DD + nb*128)*MM + ks*256;

    int lane = tid & 31, ww = tid >> 5;
    int lr = lane >> 2, lc = lane & 3;
    int wm = ww & 3, wn = ww >> 2;
    float4 acc[2][4];
#pragma unroll
    for (int i = 0; i < 2; i++)
#pragma unroll
        for (int j = 0; j < 4; j++) acc[i][j] = make_float4(0.f,0.f,0.f,0.f);

    copy_stage(sm, Ag, MM, Bg, MM, tid);
    for (int s = 0; s < 8; s++) {
        if (s < 7)
            copy_stage(sm + ((s+1)&1)*STAGE_FLOATS,
                       Ag + (s+1)*32, MM, Bg + (s+1)*32, MM, tid);
        if (s < 7) asm volatile("cp.async.wait_group 1;");
        else       asm volatile("cp.async.wait_group 0;");
        __syncthreads();
        stage_mma(sm + (s&1)*STAGE_FLOATS, acc, lane, wm, wn);
        __syncthreads();
    }

    float* Og = g_O + b*NQ*DD + nb*128;
#pragma unroll
    for (int mt = 0; mt < 2; mt++) {
#pragma unroll
        for (int nt = 0; nt < 4; nt++) {
            int row = wm*32 + mt*16 + lr;
            int col = wn*32 + nt*8 + lc*2;
            float4 d = acc[mt][nt];
            atomicAdd(Og + row*DD + col,       d.x);
            atomicAdd(Og + row*DD + col + 1,   d.y);
            atomicAdd(Og + (row+8)*DD + col,   d.z);
            atomicAdd(Og + (row+8)*DD + col+1, d.w);
        }
    }
}

// ---------------------------------------------------------------------------
// Kernel 6: normalize + scatter to output [B,X,H,W,C], float4.
// ---------------------------------------------------------------------------
__global__ __launch_bounds__(256) void k_out(float* __restrict__ out) {
    int t4 = blockIdx.x*256 + threadIdx.x;
    int t  = t4 * 4;
    int co = t & 31;
    int wo = (t >> 5) & 127;
    int xo = (t >> 15) & 31;
    int b  = t >> 20;
    int n  = xo*4 + ((wo >> 3) & 3);
    int cc = ((wo & 7)*4 + (co >> 3))*8 + (co & 7);
    float inv = __fdividef(1.f, g_rowsum[b*128 + n]);
    float4 v = *(const float4*)(g_O + (b*NQ + n)*DD + cc);
    v.x *= inv; v.y *= inv; v.z *= inv; v.w *= inv;
    *(float4*)(out + t) = v;
}

// ---------------------------------------------------------------------------
extern "C" void kernel_launch(void* const* d_in, const int* in_sizes, int n_in,
                              void* d_out, int out_size) {
    const float* storage = (const float*)d_in[0];
    const float* target  = (const float*)d_in[1];
    const float* w_cross = (const float*)d_in[2];
    const float* b_cross = (const float*)d_in[3];
    const float* w_q     = (const float*)d_in[4];
    const float* b_q     = (const float*)d_in[5];
    float* out = (float*)d_out;

    cudaFuncSetAttribute(k_conv,  cudaFuncAttributeMaxDynamicSharedMemorySize,
                         CONV_SMEM_FLOATS * 4);
    cudaFuncSetAttribute(k_gemm1, cudaFuncAttributeMaxDynamicSharedMemorySize,
                         GEMM_SMEM_BYTES);
    cudaFuncSetAttribute(k_gemm2, cudaFuncAttributeMaxDynamicSharedMemorySize,
                         GEMM_SMEM_BYTES);

    k_q    <<<512,  256>>>(target, w_q, b_q, w_cross);
    k_conv <<<1024, 256, CONV_SMEM_FLOATS*4>>>(storage, b_cross);
    k_vt   <<<1024, 256>>>();
    k_gemm1<<<128,  512, GEMM_SMEM_BYTES>>>();
    k_gemm2<<<128,  512, GEMM_SMEM_BYTES>>>();
    k_out  <<<4096, 256>>>(out);
}

// round 7
// speedup vs baseline: 1.6517x; 1.6517x over previous
#include <cuda_runtime.h>
#include <cuda_bf16.h>
#include <stdint.h>

// Problem constants
#define BB 4
#define XX 32
#define HH 8
#define WW 128
#define CC 32
#define NQ 128          // distinct query rows per batch
#define MM 4096         // key rows per batch
#define DD 256          // reduction dim

// Packed bf16x2 (low 16 = hi part, high 16 = lo part) stored in float arrays.
__device__ __align__(16) float g_Qp [BB*NQ*DD];    // [b][n][cc]
__device__ __align__(16) float g_Kp [BB*MM*DD];    // [b][m][cc]
__device__ __align__(16) float g_Vp [BB*MM*DD];    // [b][m][cc]
__device__ __align__(16) float g_Vtp[BB*DD*MM];    // [b][cc][m]
__device__ __align__(16) float g_Ep [BB*NQ*MM];    // [b][n][m] = exp(S)
__device__ __align__(16) float g_O  [BB*NQ*DD];    // fp32 accum
__device__ __align__(16) float g_rowsum[BB*NQ];
__device__ __align__(16) float g_Wh[96*72];        // presplit conv weights (tf32)
__device__ __align__(16) float g_Wl[96*72];

// ---------------------------------------------------------------------------
// helpers
// ---------------------------------------------------------------------------
__device__ __forceinline__ uint32_t f2tf(float x) {
    uint32_t h; asm("cvt.rna.tf32.f32 %0, %1;" : "=r"(h) : "f"(x)); return h;
}
__device__ __forceinline__ void sts_split(float v, float* ph, float* pl) {
    float hf = __uint_as_float(f2tf(v));
    *ph = hf;
    *pl = __uint_as_float(f2tf(v - hf));
}
// pack fp32 -> (bf16 hi, bf16 lo) in one 32-bit word (hi in low half)
__device__ __forceinline__ float pack_bf(float v) {
    __nv_bfloat16 h = __float2bfloat16(v);
    float r = v - __bfloat162float(h);
    __nv_bfloat16 l = __float2bfloat16(r);
    uint32_t w = ((uint32_t)__bfloat16_as_ushort(l) << 16) |
                 (uint32_t)__bfloat16_as_ushort(h);
    return __uint_as_float(w);
}
__device__ __forceinline__ uint32_t prmt_rep(uint32_t a, uint32_t sel) {
    uint32_t d;
    asm("prmt.b32 %0, %1, %2, %3;" : "=r"(d) : "r"(a), "r"(0u), "r"(sel));
    return d;
}
// tf32 k8 mma (conv only)
__device__ __forceinline__ void mma8(float4& d, const uint32_t* a,
                                     uint32_t b0, uint32_t b1) {
    asm volatile(
        "mma.sync.aligned.m16n8k8.row.col.f32.tf32.tf32.f32 "
        "{%0,%1,%2,%3},{%4,%5,%6,%7},{%8,%9},{%0,%1,%2,%3};"
        : "+f"(d.x), "+f"(d.y), "+f"(d.z), "+f"(d.w)
        : "r"(a[0]), "r"(a[1]), "r"(a[2]), "r"(a[3]), "r"(b0), "r"(b1));
}
// bf16 k16 mma
__device__ __forceinline__ void mma16(float4& d, const uint32_t* a,
                                      uint32_t b0, uint32_t b1) {
    asm volatile(
        "mma.sync.aligned.m16n8k16.row.col.f32.bf16.bf16.f32 "
        "{%0,%1,%2,%3},{%4,%5,%6,%7},{%8,%9},{%0,%1,%2,%3};"
        : "+f"(d.x), "+f"(d.y), "+f"(d.z), "+f"(d.w)
        : "r"(a[0]), "r"(a[1]), "r"(a[2]), "r"(a[3]), "r"(b0), "r"(b1));
}
__device__ __forceinline__ uint32_t smaddr(const void* p) {
    return (uint32_t)__cvta_generic_to_shared(p);
}
__device__ __forceinline__ void ldsm4(uint32_t r[4], const float* p) {
    uint32_t a = smaddr(p);
    asm volatile("ldmatrix.sync.aligned.m8n8.x4.shared.b16 {%0,%1,%2,%3}, [%4];"
                 : "=r"(r[0]), "=r"(r[1]), "=r"(r[2]), "=r"(r[3]) : "r"(a));
}
__device__ __forceinline__ void ldsm2(uint32_t r[2], const float* p) {
    uint32_t a = smaddr(p);
    asm volatile("ldmatrix.sync.aligned.m8n8.x2.shared.b16 {%0,%1}, [%2];"
                 : "=r"(r[0]), "=r"(r[1]) : "r"(a));
}
#define CPA(dst, src) asm volatile("cp.async.cg.shared.global [%0], [%1], 16;" \
                                   :: "r"(dst), "l"(src))
#define CP_COMMIT() asm volatile("cp.async.commit_group;")

// ---------------------------------------------------------------------------
// Kernel 1: Q projection -> packed bf16x2; zero g_O/g_rowsum; conv weights
// ---------------------------------------------------------------------------
__global__ __launch_bounds__(256) void k_q(const float* __restrict__ target,
                                           const float* __restrict__ w_q,
                                           const float* __restrict__ b_q,
                                           const float* __restrict__ w_cross) {
    int t = blockIdx.x * 256 + threadIdx.x;       // [0, 131072)
    g_O[t] = 0.f;
    if (t < BB*NQ) g_rowsum[t] = 0.f;
    if (t < 96*72) {
        int k = t / 72, o = t - k*72;
        float v = (o < 64) ? w_cross[(o*32 + (k & 31))*3 + (k >> 5)] : 0.f;
        sts_split(v, &g_Wh[t], &g_Wl[t]);
    }

    int b   = t >> 15;
    int n   = (t >> 8) & 127;
    int cc  = t & 255;
    int o   = n >> 2, whi = n & 3;
    int wlo = cc >> 3, h = cc & 7;
    int w   = whi * 32 + wlo;
    const float4* trow = (const float4*)(target + ((b*HH + h)*WW + w)*CC);
    const float4* wrow = (const float4*)(w_q + o*CC);
    float acc = b_q[o];
#pragma unroll
    for (int i = 0; i < 8; i++) {
        float4 a = trow[i], ww = wrow[i];
        acc += a.x*ww.x + a.y*ww.y + a.z*ww.z + a.w*ww.w;
    }
    g_Qp[t] = pack_bf(acc);
}

// ---------------------------------------------------------------------------
// Kernel 2: conv3d (3,1,1) im2col GEMM (3xTF32 internals, proven).
// Epilogue packs bf16x2 into g_Kp / g_Vp row-major.
// ---------------------------------------------------------------------------
#define CONV_SMEM_FLOATS (2*18*264 + 2*96*72 + 64)
__global__ __launch_bounds__(256) void k_conv(const float* __restrict__ storage,
                                              const float* __restrict__ b_cross) {
    extern __shared__ float sm[];
    float* Sh  = sm;                    // 18*264
    float* Sl  = Sh + 18*264;
    float* Wh  = Sl + 18*264;           // 96*72
    float* Wl  = Wh + 96*72;
    float* bsh = Wl + 96*72;            // 64

    int tid  = threadIdx.x;
    int bidx = blockIdx.x;              // b*256 + w*2 + xh
    int b  = bidx >> 8;
    int w  = (bidx >> 1) & 127;
    int xh = bidx & 1;
    int x0 = xh * 16;

    {
        const float4* sh4 = (const float4*)g_Wh;
        const float4* sl4 = (const float4*)g_Wl;
        float4* dh4 = (float4*)Wh;
        float4* dl4 = (float4*)Wl;
        for (int i = tid; i < 1728; i += 256) { dh4[i] = sh4[i]; dl4[i] = sl4[i]; }
    }
    if (tid < 64) bsh[tid] = b_cross[tid];

    for (int i = tid; i < 18*64; i += 256) {
        int si = i >> 6, r = i & 63;
        int c4 = (r & 7)*4, h = r >> 3;
        int xx = x0 - 1 + si;
        float4 v = make_float4(0.f, 0.f, 0.f, 0.f);
        if (xx >= 0 && xx < XX)
            v = *(const float4*)(storage + (((b*XX + xx)*HH + h)*WW + w)*CC + c4);
        float* ph = Sh + si*264 + c4*8 + h;
        float* pl = Sl + si*264 + c4*8 + h;
        sts_split(v.x, ph +  0, pl +  0);
        sts_split(v.y, ph +  8, pl +  8);
        sts_split(v.z, ph + 16, pl + 16);
        sts_split(v.w, ph + 24, pl + 24);
    }
    __syncthreads();

    int lane = tid & 31, ww = tid >> 5;
    int lr = lane >> 2, lc = lane & 3;
    int wm = ww & 3, wn = ww >> 2;      // 4m x 2n warps; warp tile 32x32
    float4 acc[2][4];
#pragma unroll
    for (int i = 0; i < 2; i++)
#pragma unroll
        for (int j = 0; j < 4; j++) acc[i][j] = make_float4(0.f,0.f,0.f,0.f);

#pragma unroll
    for (int ksl = 0; ksl < 12; ksl++) {
        int k0 = ksl*8;
        int dx = k0 >> 5, cib = k0 & 31;
        uint32_t ah[2][4], al[2][4];
#pragma unroll
        for (int mt = 0; mt < 2; mt++) {
            int rowb = wm*32 + mt*16;
            int xl = rowb >> 3;
            const float* p = Sh + (xl + dx)*264 + (cib + lc)*8 + lr;
            ah[mt][0] = __float_as_uint(p[0]);
            ah[mt][1] = __float_as_uint(p[264]);
            ah[mt][2] = __float_as_uint(p[32]);
            ah[mt][3] = __float_as_uint(p[264+32]);
            const float* q = Sl + (xl + dx)*264 + (cib + lc)*8 + lr;
            al[mt][0] = __float_as_uint(q[0]);
            al[mt][1] = __float_as_uint(q[264]);
            al[mt][2] = __float_as_uint(q[32]);
            al[mt][3] = __float_as_uint(q[264+32]);
        }
#pragma unroll
        for (int nt = 0; nt < 4; nt++) {
            int nb = wn*32 + nt*8;
            const float* p = Wh + (k0 + lc)*72 + nb + lr;
            uint32_t bh0 = __float_as_uint(p[0]);
            uint32_t bh1 = __float_as_uint(p[4*72]);
            const float* q = Wl + (k0 + lc)*72 + nb + lr;
            uint32_t bl0 = __float_as_uint(q[0]);
            uint32_t bl1 = __float_as_uint(q[4*72]);
#pragma unroll
            for (int mt = 0; mt < 2; mt++) {
                mma8(acc[mt][nt], ah[mt], bh0, bh1);
                mma8(acc[mt][nt], ah[mt], bl0, bl1);
                mma8(acc[mt][nt], al[mt], bh0, bh1);
            }
        }
    }

    int wb = w >> 5, ccb = (w & 31)*8;
#pragma unroll
    for (int mt = 0; mt < 2; mt++) {
        int rowb = wm*32 + mt*16;
        int x = x0 + (rowb >> 3);
        int h = lr;
#pragma unroll
        for (int nt = 0; nt < 4; nt++) {
            int o0 = wn*32 + nt*8 + lc*2;
            float4 d = acc[mt][nt];
            {
                float v0 = d.x + bsh[o0], v1 = d.y + bsh[o0+1];
                float* d0 = (o0     < 32) ? g_Vp : g_Kp;
                float* d1 = (o0 + 1 < 32) ? g_Vp : g_Kp;
                d0[(b*MM + (o0&31)*128     + x*4 + wb)*DD + ccb + h] = pack_bf(v0);
                d1[(b*MM + ((o0+1)&31)*128 + x*4 + wb)*DD + ccb + h] = pack_bf(v1);
            }
            {
                float v0 = d.z + bsh[o0], v1 = d.w + bsh[o0+1];
                float* d0 = (o0     < 32) ? g_Vp : g_Kp;
                float* d1 = (o0 + 1 < 32) ? g_Vp : g_Kp;
                d0[(b*MM + (o0&31)*128     + (x+1)*4 + wb)*DD + ccb + h] = pack_bf(v0);
                d1[(b*MM + ((o0+1)&31)*128 + (x+1)*4 + wb)*DD + ccb + h] = pack_bf(v1);
            }
        }
    }
}

// ---------------------------------------------------------------------------
// Kernel 3: V transpose (packed words)  [b][m][cc] -> [b][cc][m].
// ---------------------------------------------------------------------------
__global__ __launch_bounds__(256) void k_vt() {
    __shared__ float ts[64*65];
    int tid = threadIdx.x;
    int b  = blockIdx.x >> 8;
    int mt = (blockIdx.x >> 2) & 63;
    int ct = blockIdx.x & 3;
#pragma unroll
    for (int it = 0; it < 4; it++) {
        int i = tid + it*256;
        int r = i >> 4, c4 = (i & 15)*4;
        float4 v = *(const float4*)(g_Vp + (b*MM + mt*64 + r)*DD + ct*64 + c4);
        ts[r*65 + c4 + 0] = v.x; ts[r*65 + c4 + 1] = v.y;
        ts[r*65 + c4 + 2] = v.z; ts[r*65 + c4 + 3] = v.w;
    }
    __syncthreads();
#pragma unroll
    for (int it = 0; it < 4; it++) {
        int i = tid + it*256;
        int c = i >> 4, r4 = (i & 15)*4;
        float4 o = make_float4(ts[(r4+0)*65 + c], ts[(r4+1)*65 + c],
                               ts[(r4+2)*65 + c], ts[(r4+3)*65 + c]);
        *(float4*)(g_Vtp + (b*DD + ct*64 + c)*MM + mt*64 + r4) = o;
    }
}

// ---------------------------------------------------------------------------
// GEMM machinery (double-bf16): smem A tile 128x32w + B tile 64x32w, str 36.
// cp.async double-buffered; ldmatrix b16; two-pass mma.m16n8k16.bf16.
// ---------------------------------------------------------------------------
#define ASTR 36
#define STAGE_FLOATS (192*ASTR)             // 6912 floats = 27648 B
#define GEMM_SMEM_BYTES (2*STAGE_FLOATS*4)  // 55296 B

__device__ __forceinline__ void copy_stage(float* buf, const float* Ag, int lda,
                                           const float* Bg, int ldb, int tid) {
#pragma unroll
    for (int ch = 0; ch < 6; ch++) {
        int c = tid + ch*256;               // 0..1535
        int row = c >> 3, k4 = (c & 7)*4;
        if (row < 128)
            CPA(smaddr(buf + row*ASTR + k4), Ag + row*lda + k4);
        else
            CPA(smaddr(buf + row*ASTR + k4), Bg + (row-128)*ldb + k4);
    }
    CP_COMMIT();
}

// warp tile 32m x 32n (wm 0..3, wn 0..1); one 32-real-k stage
__device__ __forceinline__ void stage_mma(const float* buf, float4 acc[2][4],
                                          int lane, int wm, int wn) {
    const float* As = buf;
    const float* Bs = buf + 128*ASTR;
    int arow = (lane & 7) + ((lane >> 3) & 1)*8;
    int acol = (lane >> 4)*4;
    int bl   = lane & 15;
    int brow = bl & 7;
    int bcol = (bl >> 3)*4;
#pragma unroll
    for (int kc = 0; kc < 4; kc++) {
        int kk = kc*8;
        uint32_t ar[2][4];
#pragma unroll
        for (int mt = 0; mt < 2; mt++)
            ldsm4(ar[mt], As + (wm*32 + mt*16 + arow)*ASTR + kk + acol);
#pragma unroll
        for (int nt = 0; nt < 4; nt++) {
            uint32_t br[2];
            ldsm2(br, Bs + (wn*32 + nt*8 + brow)*ASTR + kk + bcol);
            uint32_t bh0 = prmt_rep(br[0], 0x1010u);
            uint32_t bh1 = prmt_rep(br[1], 0x1010u);
            uint32_t bL0 = prmt_rep(br[0], 0x3232u);
            uint32_t bL1 = prmt_rep(br[1], 0x3232u);
#pragma unroll
            for (int mt = 0; mt < 2; mt++) {
                mma16(acc[mt][nt], ar[mt], bh0, bh1);
                mma16(acc[mt][nt], ar[mt], bL0, bL1);
            }
        }
    }
}

// ---------------------------------------------------------------------------
// Kernel 4: S = Q @ K^T, fused exp + rowsum, E packed bf16x2 out.
// grid = b(4) x mtile(64: 64 K-rows each) = 256 CTAs. K-dim 256 (8 stages).
// ---------------------------------------------------------------------------
__global__ __launch_bounds__(256, 2) void k_gemm1() {
    extern __shared__ float sm[];
    __shared__ float srow[128];
    int tid = threadIdx.x;
    int b  = blockIdx.x >> 6;
    int mb = blockIdx.x & 63;
    const float* Ag = g_Qp + b*NQ*DD;                // [128][256]
    const float* Bg = g_Kp + (b*MM + mb*64)*DD;      // [64][256]

    int lane = tid & 31, ww = tid >> 5;
    int lr = lane >> 2, lc = lane & 3;
    int wm = ww & 3, wn = ww >> 2;                   // 4 x 2 warps
    float4 acc[2][4];
#pragma unroll
    for (int i = 0; i < 2; i++)
#pragma unroll
        for (int j = 0; j < 4; j++) acc[i][j] = make_float4(0.f,0.f,0.f,0.f);

    copy_stage(sm, Ag, DD, Bg, DD, tid);
    for (int s = 0; s < 8; s++) {
        if (s < 7)
            copy_stage(sm + ((s+1)&1)*STAGE_FLOATS,
                       Ag + (s+1)*32, DD, Bg + (s+1)*32, DD, tid);
        if (s < 7) asm volatile("cp.async.wait_group 1;");
        else       asm volatile("cp.async.wait_group 0;");
        __syncthreads();
        stage_mma(sm + (s&1)*STAGE_FLOATS, acc, lane, wm, wn);
        __syncthreads();
    }

    if (tid < 128) srow[tid] = 0.f;
    __syncthreads();
    float* Eg = g_Ep + b*NQ*MM + mb*64;
    float rs[4] = {0.f,0.f,0.f,0.f};
#pragma unroll
    for (int mt = 0; mt < 2; mt++) {
#pragma unroll
        for (int nt = 0; nt < 4; nt++) {
            int row = wm*32 + mt*16 + lr;
            int col = wn*32 + nt*8 + lc*2;
            float4 d = acc[mt][nt];
            float e0 = __expf(d.x), e1 = __expf(d.y);
            float e2 = __expf(d.z), e3 = __expf(d.w);
            rs[mt*2+0] += e0 + e1;
            rs[mt*2+1] += e2 + e3;
            *(float2*)(Eg + row*MM + col)     = make_float2(pack_bf(e0), pack_bf(e1));
            *(float2*)(Eg + (row+8)*MM + col) = make_float2(pack_bf(e2), pack_bf(e3));
        }
    }
#pragma unroll
    for (int i = 0; i < 4; i++) {
        rs[i] += __shfl_xor_sync(~0u, rs[i], 1);
        rs[i] += __shfl_xor_sync(~0u, rs[i], 2);
    }
    if (lc == 0) {
#pragma unroll
        for (int i = 0; i < 4; i++)
            atomicAdd(&srow[wm*32 + (i >> 1)*16 + (i & 1)*8 + lr], rs[i]);
    }
    __syncthreads();
    if (tid < 128) atomicAdd(&g_rowsum[b*128 + tid], srow[tid]);
}

// ---------------------------------------------------------------------------
// Kernel 5: O += E @ V, split-K(m) atomics.
// grid = b(4) x nb(4: 64-cc tiles) x ks(16: 256-k splits) = 256 CTAs.
// A = Ep [n][m]; B = Vtp [cc][m]; both packed, k-stage = 32 words.
// ---------------------------------------------------------------------------
__global__ __launch_bounds__(256, 2) void k_gemm2() {
    extern __shared__ float sm[];
    int tid = threadIdx.x;
    int b  = blockIdx.x >> 6;
    int nb = (blockIdx.x >> 4) & 3;
    int ks = blockIdx.x & 15;
    const float* Ag = g_Ep  + b*NQ*MM + ks*256;              // [128][m] ld=MM
    const float* Bg = g_Vtp + (b*DD + nb*64)*MM + ks*256;    // [64][m]  ld=MM

    int lane = tid & 31, ww = tid >> 5;
    int lr = lane >> 2, lc = lane & 3;
    int wm = ww & 3, wn = ww >> 2;
    float4 acc[2][4];
#pragma unroll
    for (int i = 0; i < 2; i++)
#pragma unroll
        for (int j = 0; j < 4; j++) acc[i][j] = make_float4(0.f,0.f,0.f,0.f);

    copy_stage(sm, Ag, MM, Bg, MM, tid);
    for (int s = 0; s < 8; s++) {
        if (s < 7)
            copy_stage(sm + ((s+1)&1)*STAGE_FLOATS,
                       Ag + (s+1)*32, MM, Bg + (s+1)*32, MM, tid);
        if (s < 7) asm volatile("cp.async.wait_group 1;");
        else       asm volatile("cp.async.wait_group 0;");
        __syncthreads();
        stage_mma(sm + (s&1)*STAGE_FLOATS, acc, lane, wm, wn);
        __syncthreads();
    }

    float* Og = g_O + b*NQ*DD + nb*64;
#pragma unroll
    for (int mt = 0; mt < 2; mt++) {
#pragma unroll
        for (int nt = 0; nt < 4; nt++) {
            int row = wm*32 + mt*16 + lr;
            int col = wn*32 + nt*8 + lc*2;
            float4 d = acc[mt][nt];
            atomicAdd(Og + row*DD + col,       d.x);
            atomicAdd(Og + row*DD + col + 1,   d.y);
            atomicAdd(Og + (row+8)*DD + col,   d.z);
            atomicAdd(Og + (row+8)*DD + col+1, d.w);
        }
    }
}

// ---------------------------------------------------------------------------
// Kernel 6: normalize + scatter to output [B,X,H,W,C], float4.
// ---------------------------------------------------------------------------
__global__ __launch_bounds__(256) void k_out(float* __restrict__ out) {
    int t4 = blockIdx.x*256 + threadIdx.x;
    int t  = t4 * 4;
    int co = t & 31;
    int wo = (t >> 5) & 127;
    int xo = (t >> 15) & 31;
    int b  = t >> 20;
    int n  = xo*4 + ((wo >> 3) & 3);
    int cc = ((wo & 7)*4 + (co >> 3))*8 + (co & 7);
    float inv = __fdividef(1.f, g_rowsum[b*128 + n]);
    float4 v = *(const float4*)(g_O + (b*NQ + n)*DD + cc);
    v.x *= inv; v.y *= inv; v.z *= inv; v.w *= inv;
    *(float4*)(out + t) = v;
}

// ---------------------------------------------------------------------------
extern "C" void kernel_launch(void* const* d_in, const int* in_sizes, int n_in,
                              void* d_out, int out_size) {
    const float* storage = (const float*)d_in[0];
    const float* target  = (const float*)d_in[1];
    const float* w_cross = (const float*)d_in[2];
    const float* b_cross = (const float*)d_in[3];
    const float* w_q     = (const float*)d_in[4];
    const float* b_q     = (const float*)d_in[5];
    float* out = (float*)d_out;

    cudaFuncSetAttribute(k_conv,  cudaFuncAttributeMaxDynamicSharedMemorySize,
                         CONV_SMEM_FLOATS * 4);
    cudaFuncSetAttribute(k_gemm1, cudaFuncAttributeMaxDynamicSharedMemorySize,
                         GEMM_SMEM_BYTES);
    cudaFuncSetAttribute(k_gemm2, cudaFuncAttributeMaxDynamicSharedMemorySize,
                         GEMM_SMEM_BYTES);

    k_q    <<<512,  256>>>(target, w_q, b_q, w_cross);
    k_conv <<<1024, 256, CONV_SMEM_FLOATS*4>>>(storage, b_cross);
    k_vt   <<<1024, 256>>>();
    k_gemm1<<<256,  256, GEMM_SMEM_BYTES>>>();
    k_gemm2<<<256,  256, GEMM_SMEM_BYTES>>>();
    k_out  <<<4096, 256>>>(out);
}

// round 8
// speedup vs baseline: 1.6601x; 1.0051x over previous
#include <cuda_runtime.h>
#include <cuda_bf16.h>
#include <stdint.h>

// Problem constants
#define BB 4
#define XX 32
#define HH 8
#define WW 128
#define CC 32
#define NQ 128          // distinct query rows per batch
#define MM 4096         // key rows per batch
#define DD 256          // reduction dim

// Packed bf16x2 (low 16 = hi part, high 16 = lo part) stored in float arrays.
__device__ __align__(16) float g_Qp [BB*NQ*DD];    // [b][n][cc]
__device__ __align__(16) float g_Kp [BB*MM*DD];    // [b][m][cc]
__device__ __align__(16) float g_Vp [BB*MM*DD];    // [b][m][cc]
__device__ __align__(16) float g_Vtp[BB*DD*MM];    // [b][cc][m]
__device__ __align__(16) float g_O  [BB*NQ*DD];    // fp32 accum
__device__ __align__(16) float g_rowsum[BB*NQ];
__device__ __align__(16) float g_Wh[96*72];        // presplit conv weights (tf32)
__device__ __align__(16) float g_Wl[96*72];

// ---------------------------------------------------------------------------
// helpers
// ---------------------------------------------------------------------------
__device__ __forceinline__ uint32_t f2tf(float x) {
    uint32_t h; asm("cvt.rna.tf32.f32 %0, %1;" : "=r"(h) : "f"(x)); return h;
}
__device__ __forceinline__ void sts_split(float v, float* ph, float* pl) {
    float hf = __uint_as_float(f2tf(v));
    *ph = hf;
    *pl = __uint_as_float(f2tf(v - hf));
}
// pack fp32 -> (bf16 hi, bf16 lo) in one 32-bit word (hi in low half)
__device__ __forceinline__ float pack_bf(float v) {
    __nv_bfloat16 h = __float2bfloat16(v);
    float r = v - __bfloat162float(h);
    __nv_bfloat16 l = __float2bfloat16(r);
    uint32_t w = ((uint32_t)__bfloat16_as_ushort(l) << 16) |
                 (uint32_t)__bfloat16_as_ushort(h);
    return __uint_as_float(w);
}
__device__ __forceinline__ uint32_t prmt_rep(uint32_t a, uint32_t sel) {
    uint32_t d;
    asm("prmt.b32 %0, %1, %2, %3;" : "=r"(d) : "r"(a), "r"(0u), "r"(sel));
    return d;
}
__device__ __forceinline__ void mma8(float4& d, const uint32_t* a,
                                     uint32_t b0, uint32_t b1) {
    asm volatile(
        "mma.sync.aligned.m16n8k8.row.col.f32.tf32.tf32.f32 "
        "{%0,%1,%2,%3},{%4,%5,%6,%7},{%8,%9},{%0,%1,%2,%3};"
        : "+f"(d.x), "+f"(d.y), "+f"(d.z), "+f"(d.w)
        : "r"(a[0]), "r"(a[1]), "r"(a[2]), "r"(a[3]), "r"(b0), "r"(b1));
}
__device__ __forceinline__ void mma16(float4& d, const uint32_t* a,
                                      uint32_t b0, uint32_t b1) {
    asm volatile(
        "mma.sync.aligned.m16n8k16.row.col.f32.bf16.bf16.f32 "
        "{%0,%1,%2,%3},{%4,%5,%6,%7},{%8,%9},{%0,%1,%2,%3};"
        : "+f"(d.x), "+f"(d.y), "+f"(d.z), "+f"(d.w)
        : "r"(a[0]), "r"(a[1]), "r"(a[2]), "r"(a[3]), "r"(b0), "r"(b1));
}
__device__ __forceinline__ uint32_t smaddr(const void* p) {
    return (uint32_t)__cvta_generic_to_shared(p);
}
__device__ __forceinline__ void ldsm4(uint32_t r[4], const float* p) {
    uint32_t a = smaddr(p);
    asm volatile("ldmatrix.sync.aligned.m8n8.x4.shared.b16 {%0,%1,%2,%3}, [%4];"
                 : "=r"(r[0]), "=r"(r[1]), "=r"(r[2]), "=r"(r[3]) : "r"(a));
}
__device__ __forceinline__ void ldsm2(uint32_t r[2], const float* p) {
    uint32_t a = smaddr(p);
    asm volatile("ldmatrix.sync.aligned.m8n8.x2.shared.b16 {%0,%1}, [%2];"
                 : "=r"(r[0]), "=r"(r[1]) : "r"(a));
}
#define CPA(dst, src) asm volatile("cp.async.cg.shared.global [%0], [%1], 16;" \
                                   :: "r"(dst), "l"(src))
#define CP_COMMIT() asm volatile("cp.async.commit_group;")

// ---------------------------------------------------------------------------
// Kernel 1: Q projection -> packed bf16x2; zero g_O/g_rowsum; conv weights
// ---------------------------------------------------------------------------
__global__ __launch_bounds__(256) void k_q(const float* __restrict__ target,
                                           const float* __restrict__ w_q,
                                           const float* __restrict__ b_q,
                                           const float* __restrict__ w_cross) {
    int t = blockIdx.x * 256 + threadIdx.x;       // [0, 131072)
    g_O[t] = 0.f;
    if (t < BB*NQ) g_rowsum[t] = 0.f;
    if (t < 96*72) {
        int k = t / 72, o = t - k*72;
        float v = (o < 64) ? w_cross[(o*32 + (k & 31))*3 + (k >> 5)] : 0.f;
        sts_split(v, &g_Wh[t], &g_Wl[t]);
    }

    int b   = t >> 15;
    int n   = (t >> 8) & 127;
    int cc  = t & 255;
    int o   = n >> 2, whi = n & 3;
    int wlo = cc >> 3, h = cc & 7;
    int w   = whi * 32 + wlo;
    const float4* trow = (const float4*)(target + ((b*HH + h)*WW + w)*CC);
    const float4* wrow = (const float4*)(w_q + o*CC);
    float acc = b_q[o];
#pragma unroll
    for (int i = 0; i < 8; i++) {
        float4 a = trow[i], ww = wrow[i];
        acc += a.x*ww.x + a.y*ww.y + a.z*ww.z + a.w*ww.w;
    }
    g_Qp[t] = pack_bf(acc);
}

// ---------------------------------------------------------------------------
// Kernel 2: conv3d (3,1,1) im2col GEMM (3xTF32). Packs bf16x2 K/V.
// ---------------------------------------------------------------------------
#define CONV_SMEM_FLOATS (2*18*264 + 2*96*72 + 64)
__global__ __launch_bounds__(256) void k_conv(const float* __restrict__ storage,
                                              const float* __restrict__ b_cross) {
    extern __shared__ float sm[];
    float* Sh  = sm;                    // 18*264
    float* Sl  = Sh + 18*264;
    float* Wh  = Sl + 18*264;           // 96*72
    float* Wl  = Wh + 96*72;
    float* bsh = Wl + 96*72;            // 64

    int tid  = threadIdx.x;
    int bidx = blockIdx.x;              // b*256 + w*2 + xh
    int b  = bidx >> 8;
    int w  = (bidx >> 1) & 127;
    int xh = bidx & 1;
    int x0 = xh * 16;

    {
        const float4* sh4 = (const float4*)g_Wh;
        const float4* sl4 = (const float4*)g_Wl;
        float4* dh4 = (float4*)Wh;
        float4* dl4 = (float4*)Wl;
        for (int i = tid; i < 1728; i += 256) { dh4[i] = sh4[i]; dl4[i] = sl4[i]; }
    }
    if (tid < 64) bsh[tid] = b_cross[tid];

    for (int i = tid; i < 18*64; i += 256) {
        int si = i >> 6, r = i & 63;
        int c4 = (r & 7)*4, h = r >> 3;
        int xx = x0 - 1 + si;
        float4 v = make_float4(0.f, 0.f, 0.f, 0.f);
        if (xx >= 0 && xx < XX)
            v = *(const float4*)(storage + (((b*XX + xx)*HH + h)*WW + w)*CC + c4);
        float* ph = Sh + si*264 + c4*8 + h;
        float* pl = Sl + si*264 + c4*8 + h;
        sts_split(v.x, ph +  0, pl +  0);
        sts_split(v.y, ph +  8, pl +  8);
        sts_split(v.z, ph + 16, pl + 16);
        sts_split(v.w, ph + 24, pl + 24);
    }
    __syncthreads();

    int lane = tid & 31, ww = tid >> 5;
    int lr = lane >> 2, lc = lane & 3;
    int wm = ww & 3, wn = ww >> 2;      // 4m x 2n warps; warp tile 32x32
    float4 acc[2][4];
#pragma unroll
    for (int i = 0; i < 2; i++)
#pragma unroll
        for (int j = 0; j < 4; j++) acc[i][j] = make_float4(0.f,0.f,0.f,0.f);

#pragma unroll
    for (int ksl = 0; ksl < 12; ksl++) {
        int k0 = ksl*8;
        int dx = k0 >> 5, cib = k0 & 31;
        uint32_t ah[2][4], al[2][4];
#pragma unroll
        for (int mt = 0; mt < 2; mt++) {
            int rowb = wm*32 + mt*16;
            int xl = rowb >> 3;
            const float* p = Sh + (xl + dx)*264 + (cib + lc)*8 + lr;
            ah[mt][0] = __float_as_uint(p[0]);
            ah[mt][1] = __float_as_uint(p[264]);
            ah[mt][2] = __float_as_uint(p[32]);
            ah[mt][3] = __float_as_uint(p[264+32]);
            const float* q = Sl + (xl + dx)*264 + (cib + lc)*8 + lr;
            al[mt][0] = __float_as_uint(q[0]);
            al[mt][1] = __float_as_uint(q[264]);
            al[mt][2] = __float_as_uint(q[32]);
            al[mt][3] = __float_as_uint(q[264+32]);
        }
#pragma unroll
        for (int nt = 0; nt < 4; nt++) {
            int nb = wn*32 + nt*8;
            const float* p = Wh + (k0 + lc)*72 + nb + lr;
            uint32_t bh0 = __float_as_uint(p[0]);
            uint32_t bh1 = __float_as_uint(p[4*72]);
            const float* q = Wl + (k0 + lc)*72 + nb + lr;
            uint32_t bl0 = __float_as_uint(q[0]);
            uint32_t bl1 = __float_as_uint(q[4*72]);
#pragma unroll
            for (int mt = 0; mt < 2; mt++) {
                mma8(acc[mt][nt], ah[mt], bh0, bh1);
                mma8(acc[mt][nt], ah[mt], bl0, bl1);
                mma8(acc[mt][nt], al[mt], bh0, bh1);
            }
        }
    }

    int wb = w >> 5, ccb = (w & 31)*8;
#pragma unroll
    for (int mt = 0; mt < 2; mt++) {
        int rowb = wm*32 + mt*16;
        int x = x0 + (rowb >> 3);
        int h = lr;
#pragma unroll
        for (int nt = 0; nt < 4; nt++) {
            int o0 = wn*32 + nt*8 + lc*2;
            float4 d = acc[mt][nt];
            {
                float v0 = d.x + bsh[o0], v1 = d.y + bsh[o0+1];
                float* d0 = (o0     < 32) ? g_Vp : g_Kp;
                float* d1 = (o0 + 1 < 32) ? g_Vp : g_Kp;
                d0[(b*MM + (o0&31)*128     + x*4 + wb)*DD + ccb + h] = pack_bf(v0);
                d1[(b*MM + ((o0+1)&31)*128 + x*4 + wb)*DD + ccb + h] = pack_bf(v1);
            }
            {
                float v0 = d.z + bsh[o0], v1 = d.w + bsh[o0+1];
                float* d0 = (o0     < 32) ? g_Vp : g_Kp;
                float* d1 = (o0 + 1 < 32) ? g_Vp : g_Kp;
                d0[(b*MM + (o0&31)*128     + (x+1)*4 + wb)*DD + ccb + h] = pack_bf(v0);
                d1[(b*MM + ((o0+1)&31)*128 + (x+1)*4 + wb)*DD + ccb + h] = pack_bf(v1);
            }
        }
    }
}

// ---------------------------------------------------------------------------
// Kernel 3: V transpose (packed words)  [b][m][cc] -> [b][cc][m].
// ---------------------------------------------------------------------------
__global__ __launch_bounds__(256) void k_vt() {
    __shared__ float ts[64*65];
    int tid = threadIdx.x;
    int b  = blockIdx.x >> 8;
    int mt = (blockIdx.x >> 2) & 63;
    int ct = blockIdx.x & 3;
#pragma unroll
    for (int it = 0; it < 4; it++) {
        int i = tid + it*256;
        int r = i >> 4, c4 = (i & 15)*4;
        float4 v = *(const float4*)(g_Vp + (b*MM + mt*64 + r)*DD + ct*64 + c4);
        ts[r*65 + c4 + 0] = v.x; ts[r*65 + c4 + 1] = v.y;
        ts[r*65 + c4 + 2] = v.z; ts[r*65 + c4 + 3] = v.w;
    }
    __syncthreads();
#pragma unroll
    for (int it = 0; it < 4; it++) {
        int i = tid + it*256;
        int c = i >> 4, r4 = (i & 15)*4;
        float4 o = make_float4(ts[(r4+0)*65 + c], ts[(r4+1)*65 + c],
                               ts[(r4+2)*65 + c], ts[(r4+3)*65 + c]);
        *(float4*)(g_Vtp + (b*DD + ct*64 + c)*MM + mt*64 + r4) = o;
    }
}

// ---------------------------------------------------------------------------
// Fused attention kernel machinery
// smem layout (floats): [0 : 13824) phase1 double-buf (A128+B64 x 36 x2),
//                       later reused as two Vt panels (64x68 each @ 0 / 4352);
//                       [13824 : 22528) Esm (128 x 68 packed words).
// ---------------------------------------------------------------------------
#define ASTR 36
#define ESTR 68
#define STAGE_FLOATS (192*ASTR)             // 6912
#define ESM_OFF (2*STAGE_FLOATS)            // 13824
#define ATTN_SMEM_BYTES ((ESM_OFF + 128*ESTR)*4)   // 90112 B

__device__ __forceinline__ void copy_stage(float* buf, const float* Ag, int lda,
                                           const float* Bg, int ldb, int tid) {
#pragma unroll
    for (int ch = 0; ch < 6; ch++) {
        int c = tid + ch*256;               // 0..1535
        int row = c >> 3, k4 = (c & 7)*4;
        if (row < 128)
            CPA(smaddr(buf + row*ASTR + k4), Ag + row*lda + k4);
        else
            CPA(smaddr(buf + row*ASTR + k4), Bg + (row-128)*ldb + k4);
    }
    CP_COMMIT();
}

// generic double-bf16 mma block: A rows (wm*32..+31), B rows (wn*32..+31)
__device__ __forceinline__ void mma_block(const float* As, int astr,
                                          const float* Bs, int bstr,
                                          int nkc, float4 acc[2][4],
                                          int lane, int wm, int wn) {
    int arow = (lane & 7) + ((lane >> 3) & 1)*8;
    int acol = (lane >> 4)*4;
    int bl   = lane & 15;
    int brow = bl & 7;
    int bcol = (bl >> 3)*4;
    for (int kc = 0; kc < nkc; kc++) {
        int kk = kc*8;
        uint32_t ar[2][4];
#pragma unroll
        for (int mt = 0; mt < 2; mt++)
            ldsm4(ar[mt], As + (wm*32 + mt*16 + arow)*astr + kk + acol);
#pragma unroll
        for (int nt = 0; nt < 4; nt++) {
            uint32_t br[2];
            ldsm2(br, Bs + (wn*32 + nt*8 + brow)*bstr + kk + bcol);
            uint32_t bh0 = prmt_rep(br[0], 0x1010u);
            uint32_t bh1 = prmt_rep(br[1], 0x1010u);
            uint32_t bL0 = prmt_rep(br[0], 0x3232u);
            uint32_t bL1 = prmt_rep(br[1], 0x3232u);
#pragma unroll
            for (int mt = 0; mt < 2; mt++) {
                mma16(acc[mt][nt], ar[mt], bh0, bh1);
                mma16(acc[mt][nt], ar[mt], bL0, bL1);
            }
        }
    }
}

// ---------------------------------------------------------------------------
// Kernel 4: fused attention. grid = b(4) x mchunk(64 of 64 keys) = 256 CTAs.
// Phase 1: S = Q @ K_chunk^T (128x64, K=256); exp -> Esm (smem) + rowsum.
// Phase 2: O += E @ V_chunk (128x256, K=64) via 4 Vt panels, split-K atomics.
// ---------------------------------------------------------------------------
__global__ __launch_bounds__(256, 2) void k_attn() {
    extern __shared__ float sm[];
    __shared__ float srow[128];
    float* Esm = sm + ESM_OFF;
    int tid = threadIdx.x;
    int b  = blockIdx.x >> 6;
    int mb = blockIdx.x & 63;
    const float* Ag = g_Qp + b*NQ*DD;                // [128][256w]
    const float* Bg = g_Kp + (b*MM + mb*64)*DD;      // [64][256w]

    int lane = tid & 31, ww = tid >> 5;
    int lr = lane >> 2, lc = lane & 3;
    int wm = ww & 3, wn = ww >> 2;                   // 4m x 2n warps
    float4 acc[2][4];
#pragma unroll
    for (int i = 0; i < 2; i++)
#pragma unroll
        for (int j = 0; j < 4; j++) acc[i][j] = make_float4(0.f,0.f,0.f,0.f);

    // ---- Phase 1 mainloop ----
    copy_stage(sm, Ag, DD, Bg, DD, tid);
    for (int s = 0; s < 8; s++) {
        if (s < 7)
            copy_stage(sm + ((s+1)&1)*STAGE_FLOATS,
                       Ag + (s+1)*32, DD, Bg + (s+1)*32, DD, tid);
        if (s < 7) asm volatile("cp.async.wait_group 1;");
        else       asm volatile("cp.async.wait_group 0;");
        __syncthreads();
        mma_block(sm + (s&1)*STAGE_FLOATS, ASTR,
                  sm + (s&1)*STAGE_FLOATS + 128*ASTR, ASTR,
                  4, acc, lane, wm, wn);
        __syncthreads();
    }

    // ---- prefetch Vt panel 0 into dead phase-1 buffer region ----
    {
        const float* Vg = g_Vtp + (b*DD + 0)*MM + mb*64;   // [64 rows][64w]
#pragma unroll
        for (int ch = 0; ch < 4; ch++) {
            int c = tid + ch*256;           // 0..1023
            int row = c >> 4, f4 = (c & 15)*4;
            CPA(smaddr(sm + row*ESTR + f4), Vg + row*MM + f4);
        }
        CP_COMMIT();
    }

    // ---- Phase 1 epilogue: exp, rowsum, pack E into Esm ----
    if (tid < 128) srow[tid] = 0.f;
    __syncthreads();
    float rs[4] = {0.f,0.f,0.f,0.f};
#pragma unroll
    for (int mt = 0; mt < 2; mt++) {
#pragma unroll
        for (int nt = 0; nt < 4; nt++) {
            int row = wm*32 + mt*16 + lr;
            int col = wn*32 + nt*8 + lc*2;
            float4 d = acc[mt][nt];
            float e0 = __expf(d.x), e1 = __expf(d.y);
            float e2 = __expf(d.z), e3 = __expf(d.w);
            rs[mt*2+0] += e0 + e1;
            rs[mt*2+1] += e2 + e3;
            Esm[row*ESTR + col]       = pack_bf(e0);
            Esm[row*ESTR + col + 1]   = pack_bf(e1);
            Esm[(row+8)*ESTR + col]   = pack_bf(e2);
            Esm[(row+8)*ESTR + col+1] = pack_bf(e3);
        }
    }
#pragma unroll
    for (int i = 0; i < 4; i++) {
        rs[i] += __shfl_xor_sync(~0u, rs[i], 1);
        rs[i] += __shfl_xor_sync(~0u, rs[i], 2);
    }
    if (lc == 0) {
#pragma unroll
        for (int i = 0; i < 4; i++)
            atomicAdd(&srow[wm*32 + (i >> 1)*16 + (i & 1)*8 + lr], rs[i]);
    }
    __syncthreads();
    if (tid < 128) atomicAdd(&g_rowsum[b*128 + tid], srow[tid]);

    // ---- Phase 2: 4 cc-blocks of 64, Vt panels double-buffered ----
    for (int cb = 0; cb < 4; cb++) {
        if (cb < 3) {
            const float* Vg = g_Vtp + (b*DD + (cb+1)*64)*MM + mb*64;
            float* pan = sm + ((cb+1)&1)*(64*ESTR);
#pragma unroll
            for (int ch = 0; ch < 4; ch++) {
                int c = tid + ch*256;
                int row = c >> 4, f4 = (c & 15)*4;
                CPA(smaddr(pan + row*ESTR + f4), Vg + row*MM + f4);
            }
            CP_COMMIT();
        }
        if (cb < 3) asm volatile("cp.async.wait_group 1;");
        else        asm volatile("cp.async.wait_group 0;");
        __syncthreads();

        float4 acc2[2][4];
#pragma unroll
        for (int i = 0; i < 2; i++)
#pragma unroll
            for (int j = 0; j < 4; j++) acc2[i][j] = make_float4(0.f,0.f,0.f,0.f);

        mma_block(Esm, ESTR, sm + (cb&1)*(64*ESTR), ESTR,
                  8, acc2, lane, wm, wn);

        float* Og = g_O + b*NQ*DD + cb*64;
#pragma unroll
        for (int mt = 0; mt < 2; mt++) {
#pragma unroll
            for (int nt = 0; nt < 4; nt++) {
                int row = wm*32 + mt*16 + lr;
                int col = wn*32 + nt*8 + lc*2;
                float4 d = acc2[mt][nt];
                atomicAdd(Og + row*DD + col,       d.x);
                atomicAdd(Og + row*DD + col + 1,   d.y);
                atomicAdd(Og + (row+8)*DD + col,   d.z);
                atomicAdd(Og + (row+8)*DD + col+1, d.w);
            }
        }
        __syncthreads();
    }
}

// ---------------------------------------------------------------------------
// Kernel 5: normalize + scatter to output [B,X,H,W,C], float4.
// ---------------------------------------------------------------------------
__global__ __launch_bounds__(256) void k_out(float* __restrict__ out) {
    int t4 = blockIdx.x*256 + threadIdx.x;
    int t  = t4 * 4;
    int co = t & 31;
    int wo = (t >> 5) & 127;
    int xo = (t >> 15) & 31;
    int b  = t >> 20;
    int n  = xo*4 + ((wo >> 3) & 3);
    int cc = ((wo & 7)*4 + (co >> 3))*8 + (co & 7);
    float inv = __fdividef(1.f, g_rowsum[b*128 + n]);
    float4 v = *(const float4*)(g_O + (b*NQ + n)*DD + cc);
    v.x *= inv; v.y *= inv; v.z *= inv; v.w *= inv;
    *(float4*)(out + t) = v;
}

// ---------------------------------------------------------------------------
extern "C" void kernel_launch(void* const* d_in, const int* in_sizes, int n_in,
                              void* d_out, int out_size) {
    const float* storage = (const float*)d_in[0];
    const float* target  = (const float*)d_in[1];
    const float* w_cross = (const float*)d_in[2];
    const float* b_cross = (const float*)d_in[3];
    const float* w_q     = (const float*)d_in[4];
    const float* b_q     = (const float*)d_in[5];
    float* out = (float*)d_out;

    cudaFuncSetAttribute(k_conv,  cudaFuncAttributeMaxDynamicSharedMemorySize,
                         CONV_SMEM_FLOATS * 4);
    cudaFuncSetAttribute(k_attn,  cudaFuncAttributeMaxDynamicSharedMemorySize,
                         ATTN_SMEM_BYTES);

    k_q    <<<512,  256>>>(target, w_q, b_q, w_cross);
    k_conv <<<1024, 256, CONV_SMEM_FLOATS*4>>>(storage, b_cross);
    k_vt   <<<1024, 256>>>();
    k_attn <<<256,  256, ATTN_SMEM_BYTES>>>();
    k_out  <<<4096, 256>>>(out);
}